// round 6
// baseline (speedup 1.0000x reference)
#include <cuda_runtime.h>
#include <cstdint>

#define Bn 16
#define Cn 80
#define Hn 128
#define Wn 128
#define HWn 16384
#define Kn 100
#define NUMD 1000
#define SEGS 32
#define HI_CAP 65536
#define CAND_CAP 262144
#define PAIR_CAP 16384
#define COMP_CAP 2048
#define SCORE_THR 0.05f
#define IOU_THR 0.5f
#define DIST_THR 0.5f
#define THR_HI 3.2f
#define TOTB (2 * Bn * Cn)
#define WT 1024   /* worker threads */

typedef unsigned long long u64;
typedef unsigned int u32;

#define NEG_INF __int_as_float(0xff800000)

// ---------------- device scratch (zero-initialized at load) ----------------
__device__ u64 g_hi[SEGS][HI_CAP];
__device__ int g_cnt[SEGS];
__device__ u64 g_low[SEGS][CAND_CAP];   // slow-path only
__device__ int g_cnt_low[SEGS];
__device__ u64 g_pairpos[Bn][PAIR_CAP]; // pair-sort overflow fallback

// ---------------- helpers ----------------
__device__ __forceinline__ u32 map_f(float f) {
    u32 u = __float_as_uint(f);
    return (u & 0x80000000u) ? ~u : (u | 0x80000000u);
}
__device__ __forceinline__ float sigmoidf_dev(float x) {
    if (x >= 0.f) return 1.f / (1.f + expf(-x));
    float e = expf(x);
    return e / (1.f + e);
}
__device__ __forceinline__ u64 make_key(float raw, u32 idx) {
    float s = sigmoidf_dev(raw);
    return ((u64)(__float_as_uint(s) | 0x80000000u) << 32) |
           (u64)(0xFFFFFFFFu - idx);
}

// ascending bitonic sort of n (power of 2) u64 keys, nt threads (fallback only)
__device__ __forceinline__ void bitonic_sort(u64* d, int n, int tid, int nt) {
    for (int k = 2; k <= n; k <<= 1) {
        for (int j = k >> 1; j > 0; j >>= 1) {
            for (int t = tid; t < n; t += nt) {
                int ixj = t ^ j;
                if (ixj > t) {
                    u64 a = d[t], b = d[ixj];
                    bool asc = ((t & k) == 0);
                    if ((a > b) == asc) { d[t] = b; d[ixj] = a; }
                }
            }
            __syncthreads();
        }
    }
}

// ================= K1: local-max + threshold (MLP-4 chunks) =================
__global__ void __launch_bounds__(256, 4)
k_localmax(const float* __restrict__ tl, const float* __restrict__ br) {
    const int plane = blockIdx.x;
    const int h = plane / (Bn * Cn);
    const int rem = plane % (Bn * Cn);
    const int pb = rem / Cn;
    const int pc = rem % Cn;
    const int seg = h * Bn + pb;
    const float* src = (h == 0 ? tl : br) + (size_t)rem * HWn;

    const int tid = threadIdx.x;
    const int warp = tid >> 5;
    const int lane = tid & 31;
    const int r0 = warp * 16;
    const float4* row4 = (const float4*)src;

    auto hmax4 = [&](float4 v) -> float4 {
        float left  = __shfl_up_sync(0xffffffffu, v.w, 1);
        float right = __shfl_down_sync(0xffffffffu, v.x, 1);
        if (lane == 0)  left  = NEG_INF;
        if (lane == 31) right = NEG_INF;
        float4 r;
        r.x = fmaxf(fmaxf(left, v.x), v.y);
        r.y = fmaxf(fmaxf(v.x, v.y), v.z);
        r.z = fmaxf(fmaxf(v.y, v.z), v.w);
        r.w = fmaxf(fmaxf(v.z, v.w), right);
        return r;
    };

    auto emit = [&](float v, float m, u32 idx) {
        if (v >= m) {
            int p = atomicAdd(&g_cnt[seg], 1);
            if (p < HI_CAP) g_hi[seg][p] = make_key(v, idx);
        }
    };

    float4 prev;
    float4 vcarry = row4[r0 * 32 + lane];
    if (r0 > 0) prev = hmax4(row4[(r0 - 1) * 32 + lane]);
    else prev = make_float4(NEG_INF, NEG_INF, NEG_INF, NEG_INF);
    float4 hcarry = hmax4(vcarry);

    #pragma unroll
    for (int c = 0; c < 4; ++c) {
        const int y = r0 + 4 * c;
        float4 va = row4[(y + 1) * 32 + lane];
        float4 vb = row4[(y + 2) * 32 + lane];
        float4 vc = row4[(y + 3) * 32 + lane];
        float4 vd;
        bool has4 = (y + 4) < Hn;
        if (has4) vd = row4[(y + 4) * 32 + lane];

        float4 h1 = hmax4(va);
        float4 h2 = hmax4(vb);
        float4 h3 = hmax4(vc);
        float4 h4 = has4 ? hmax4(vd)
                         : make_float4(NEG_INF, NEG_INF, NEG_INF, NEG_INF);

        float4 w0, w1, w2, w3;
        w0.x = fmaxf(fmaxf(fmaxf(prev.x, hcarry.x), h1.x), THR_HI);
        w0.y = fmaxf(fmaxf(fmaxf(prev.y, hcarry.y), h1.y), THR_HI);
        w0.z = fmaxf(fmaxf(fmaxf(prev.z, hcarry.z), h1.z), THR_HI);
        w0.w = fmaxf(fmaxf(fmaxf(prev.w, hcarry.w), h1.w), THR_HI);
        w1.x = fmaxf(fmaxf(fmaxf(hcarry.x, h1.x), h2.x), THR_HI);
        w1.y = fmaxf(fmaxf(fmaxf(hcarry.y, h1.y), h2.y), THR_HI);
        w1.z = fmaxf(fmaxf(fmaxf(hcarry.z, h1.z), h2.z), THR_HI);
        w1.w = fmaxf(fmaxf(fmaxf(hcarry.w, h1.w), h2.w), THR_HI);
        w2.x = fmaxf(fmaxf(fmaxf(h1.x, h2.x), h3.x), THR_HI);
        w2.y = fmaxf(fmaxf(fmaxf(h1.y, h2.y), h3.y), THR_HI);
        w2.z = fmaxf(fmaxf(fmaxf(h1.z, h2.z), h3.z), THR_HI);
        w2.w = fmaxf(fmaxf(fmaxf(h1.w, h2.w), h3.w), THR_HI);
        w3.x = fmaxf(fmaxf(fmaxf(h2.x, h3.x), h4.x), THR_HI);
        w3.y = fmaxf(fmaxf(fmaxf(h2.y, h3.y), h4.y), THR_HI);
        w3.z = fmaxf(fmaxf(fmaxf(h2.z, h3.z), h4.z), THR_HI);
        w3.w = fmaxf(fmaxf(fmaxf(h2.w, h3.w), h4.w), THR_HI);

        bool any = (vcarry.x >= w0.x) | (vcarry.y >= w0.y) | (vcarry.z >= w0.z) | (vcarry.w >= w0.w) |
                   (va.x >= w1.x) | (va.y >= w1.y) | (va.z >= w1.z) | (va.w >= w1.w) |
                   (vb.x >= w2.x) | (vb.y >= w2.y) | (vb.z >= w2.z) | (vb.w >= w2.w) |
                   (vc.x >= w3.x) | (vc.y >= w3.y) | (vc.z >= w3.z) | (vc.w >= w3.w);

        if (__ballot_sync(0xffffffffu, any)) {
            if (any) {
                u32 ib = (u32)(pc * HWn + y * Wn + lane * 4);
                emit(vcarry.x, w0.x, ib + 0);
                emit(vcarry.y, w0.y, ib + 1);
                emit(vcarry.z, w0.z, ib + 2);
                emit(vcarry.w, w0.w, ib + 3);
                emit(va.x, w1.x, ib + Wn + 0);
                emit(va.y, w1.y, ib + Wn + 1);
                emit(va.z, w1.z, ib + Wn + 2);
                emit(va.w, w1.w, ib + Wn + 3);
                emit(vb.x, w2.x, ib + 2 * Wn + 0);
                emit(vb.y, w2.y, ib + 2 * Wn + 1);
                emit(vb.z, w2.z, ib + 2 * Wn + 2);
                emit(vb.w, w2.w, ib + 2 * Wn + 3);
                emit(vc.x, w3.x, ib + 3 * Wn + 0);
                emit(vc.y, w3.y, ib + 3 * Wn + 1);
                emit(vc.z, w3.z, ib + 3 * Wn + 2);
                emit(vc.w, w3.w, ib + 3 * Wn + 3);
            }
        }

        prev = h3; hcarry = h4; vcarry = vd;
    }
}

// ================= K2: worker — rank-select + pair + NMS + output =================
__global__ void __launch_bounds__(WT)
k_worker(const float* __restrict__ tl_heat, const float* __restrict__ br_heat,
         const float* __restrict__ tl_off, const float* __restrict__ br_off,
         const float* __restrict__ tl_emb, const float* __restrict__ br_emb,
         const int* __restrict__ inp_h, const int* __restrict__ inp_w,
         float* __restrict__ out) {
    __shared__ u64 comp[COMP_CAP];
    __shared__ u64 sel[Kn];
    __shared__ float ts[Kn], tx[Kn], ty[Kn], te[Kn];
    __shared__ float bs_[Kn], bx[Kn], by[Kn], be[Kn];
    __shared__ int tc[Kn], bc[Kn];
    __shared__ float x1[NUMD], y1[NUMD], x2[NUMD], y2[NUMD], sc[NUMD];
    __shared__ unsigned char cl[NUMD], kp[NUMD];
    __shared__ short idxs[Kn];
    __shared__ int s_np, s_num;

    const int b = blockIdx.x;
    const int tid = threadIdx.x;
    const float wr = (float)(*inp_w) / (float)Wn;
    const float hr = (float)(*inp_h) / (float)Hn;

    // ---------------- phase 2: per-segment top-100 via rank-select ----------------
    for (int pass = 0; pass < 2; ++pass) {
        const int seg = pass * Bn + b;
        const int mhi = g_cnt[seg];

        if (mhi >= Kn && mhi <= COMP_CAP) {
            // load keys to smem
            for (int i = tid; i < mhi; i += WT) comp[i] = g_hi[seg][i];
            __syncthreads();
            // each thread caches up to 2 keys; rank = #keys greater
            u64 k0v = 0ull, k1v = 0ull;
            bool h0 = tid < mhi, h1 = tid + WT < mhi;
            if (h0) k0v = comp[tid];
            if (h1) k1v = comp[tid + WT];
            int r0c = 0, r1c = 0;
            int j = 0;
            for (; j + 4 <= mhi; j += 4) {
                u64 a = comp[j], bq = comp[j + 1], cq = comp[j + 2], dq = comp[j + 3];
                r0c += (a > k0v) + (bq > k0v) + (cq > k0v) + (dq > k0v);
                r1c += (a > k1v) + (bq > k1v) + (cq > k1v) + (dq > k1v);
            }
            for (; j < mhi; ++j) {
                u64 a = comp[j];
                r0c += (a > k0v);
                r1c += (a > k1v);
            }
            if (h0 && r0c < Kn) sel[r0c] = k0v;
            if (h1 && r1c < Kn) sel[r1c] = k1v;
            __syncthreads();
        } else {
            // slow path (never taken on normal data): full recompute + 100x max
            const float* heat = (pass ? br_heat : tl_heat) + (size_t)(b * Cn) * HWn;
            if (tid == 0) g_cnt_low[seg] = 0;
            __syncthreads();
            for (int e = tid; e < Cn * HWn; e += WT) {
                int cc = e >> 14;
                int ind = e & (HWn - 1);
                int y = ind >> 7, x = ind & 127;
                const float* pl = heat + (size_t)cc * HWn;
                float v = pl[ind];
                int y0 = y > 0 ? y - 1 : 0, y1b = y < 127 ? y + 1 : 127;
                int x0 = x > 0 ? x - 1 : 0, x1b = x < 127 ? x + 1 : 127;
                bool mx = true;
                for (int yy = y0; yy <= y1b; ++yy)
                    for (int xx = x0; xx <= x1b; ++xx)
                        mx &= (v >= pl[yy * Wn + xx]);
                if (mx) {
                    int p = atomicAdd(&g_cnt_low[seg], 1);
                    if (p < CAND_CAP) g_low[seg][p] = make_key(v, (u32)(cc * HWn + ind));
                }
            }
            __syncthreads();
            int Mc = g_cnt_low[seg];
            if (Mc > CAND_CAP) Mc = CAND_CAP;
            u64* rk = comp;
            int* ri = (int*)(comp + WT);
            for (int r = 0; r < Kn; ++r) {
                u64 best = 0ull; int bidx = -1;
                for (int i = tid; i < Mc; i += WT) {
                    u64 v = g_low[seg][i];
                    if (v > best) { best = v; bidx = i; }
                }
                rk[tid] = best; ri[tid] = bidx;
                __syncthreads();
                for (int s = WT / 2; s > 0; s >>= 1) {
                    if (tid < s && rk[tid + s] > rk[tid]) {
                        rk[tid] = rk[tid + s]; ri[tid] = ri[tid + s];
                    }
                    __syncthreads();
                }
                if (tid == 0) {
                    sel[r] = rk[0];
                    if (ri[0] >= 0) g_low[seg][ri[0]] = 0ull;
                }
                __syncthreads();
            }
        }

        if (tid < Kn) {
            u64 key = sel[tid];
            u32 m = (u32)(key >> 32);
            float score = __uint_as_float(m & 0x7FFFFFFFu);
            u32 idx = 0xFFFFFFFFu - (u32)(key & 0xFFFFFFFFu);
            if (key == 0ull) { idx = 0u; score = 0.f; }
            int cls = idx / HWn;
            int ind = idx % HWn;
            int yy = ind >> 7, xx = ind & 127;
            const float* offp = pass ? br_off : tl_off;
            const float* embp = pass ? br_emb : tl_emb;
            float ox = offp[((size_t)(b * 2 + 0) * HWn) + ind];
            float oy = offp[((size_t)(b * 2 + 1) * HWn) + ind];
            float em = embp[(size_t)b * HWn + ind];
            float xs = fmaxf(((float)xx + ox) * wr, 0.f);
            float ys = fmaxf(((float)yy + oy) * hr, 0.f);
            if (pass == 0) {
                ts[tid] = score; tx[tid] = xs; ty[tid] = ys; te[tid] = em; tc[tid] = cls;
            } else {
                bs_[tid] = score; bx[tid] = xs; by[tid] = ys; be[tid] = em; bc[tid] = cls;
            }
        }
        __syncthreads();
    }

    // ---------------- phase 3: pairing + positive compaction + rank order + NMS ----------------
    if (tid == 0) s_np = 0;
    __syncthreads();

    for (int t = tid; t < Kn * Kn; t += WT) {
        int i = t / Kn, j = t % Kn;
        float scv = (ts[i] + bs_[j]) * 0.5f;
        bool neg = (tc[i] != bc[j]) || (bx[j] <= tx[i]) || (by[j] <= ty[i]) ||
                   (fabsf(te[i] - be[j]) > DIST_THR);
        if (!neg && scv > SCORE_THR) {
            int p = atomicAdd(&s_np, 1);
            u64 key = ((u64)map_f(scv) << 32) | (u64)(0xFFFFFFFFu - (u32)t);
            if (p < PAIR_CAP) g_pairpos[b][p] = key;
            if (p < COMP_CAP) comp[p] = key;
        }
    }
    __syncthreads();

    int np = s_np < PAIR_CAP ? s_np : PAIR_CAP;
    int m = np < NUMD ? np : NUMD;
    if (np > 0) {
        if (np <= COMP_CAP) {
            // rank-order positives via broadcast loop (np typically ~12)
            u64 k0v = 0ull, k1v = 0ull;
            bool h0 = tid < np, h1 = tid + WT < np;
            if (h0) k0v = comp[tid];
            if (h1) k1v = comp[tid + WT];
            int r0c = 0, r1c = 0;
            for (int j = 0; j < np; ++j) {
                u64 a = comp[j];
                r0c += (a > k0v);
                r1c += (a > k1v);
            }
            __syncthreads();
            auto place = [&](u64 key, int r) {
                if (r < NUMD) {
                    u32 mm = (u32)(key >> 32);
                    float scv = __uint_as_float(mm & 0x7FFFFFFFu);
                    u32 t = 0xFFFFFFFFu - (u32)(key & 0xFFFFFFFFu);
                    int i = t / Kn, j = t % Kn;
                    x1[r] = tx[i]; y1[r] = ty[i]; x2[r] = bx[j]; y2[r] = by[j];
                    sc[r] = scv;
                    cl[r] = (unsigned char)tc[i];
                    kp[r] = 1;
                }
            };
            if (h0) place(k0v, r0c);
            if (h1) place(k1v, r1c);
            __syncthreads();
        } else {
            // fallback: global bitonic (never taken on normal data)
            u64* arr = g_pairpos[b];
            int n2 = 2;
            while (n2 < np) n2 <<= 1;
            for (int t = np + tid; t < n2; t += WT) arr[t] = 0ull;
            __syncthreads();
            bitonic_sort(arr, n2, tid, WT);
            for (int r = tid; r < m; r += WT) {
                u64 key = arr[n2 - 1 - r];
                u32 mm = (u32)(key >> 32);
                float scv = __uint_as_float(mm & 0x7FFFFFFFu);
                u32 t = 0xFFFFFFFFu - (u32)(key & 0xFFFFFFFFu);
                int i = t / Kn, j = t % Kn;
                x1[r] = tx[i]; y1[r] = ty[i]; x2[r] = bx[j]; y2[r] = by[j];
                sc[r] = scv;
                cl[r] = (unsigned char)tc[i];
                kp[r] = 1;
            }
            __syncthreads();
        }

        // greedy NMS over m sorted valid detections
        for (int i = 0; i < m; i++) {
            if (kp[i]) {
                float xi1 = x1[i], yi1 = y1[i], xi2 = x2[i], yi2 = y2[i];
                float ai = fmaxf(xi2 - xi1, 0.f) * fmaxf(yi2 - yi1, 0.f);
                unsigned char ci = cl[i];
                for (int j = i + 1 + tid; j < m; j += WT) {
                    if (kp[j] && cl[j] == ci) {
                        float aj = fmaxf(x2[j] - x1[j], 0.f) * fmaxf(y2[j] - y1[j], 0.f);
                        float iw = fmaxf(fminf(xi2, x2[j]) - fmaxf(xi1, x1[j]), 0.f);
                        float ih = fmaxf(fminf(yi2, y2[j]) - fmaxf(yi1, y1[j]), 0.f);
                        float inter = iw * ih;
                        float iou = inter / fmaxf(ai + aj - inter, 1e-6f);
                        if (iou > IOU_THR) kp[j] = 0;
                    }
                }
            }
            __syncthreads();
        }

        if (tid == 0) {
            int cnt = 0;
            for (int i = 0; i < m; i++) {
                if (kp[i]) {
                    if (cnt < Kn) idxs[cnt] = (short)i;
                    cnt++;
                }
            }
            s_num = cnt < Kn ? cnt : Kn;
        }
    } else {
        if (tid == 0) s_num = 0;
    }
    __syncthreads();

    // ---------------- output ----------------
    const int num = s_num;
    if (tid == 0) out[b] = (float)num;

    float* pb = out + Bn;
    float* ps = out + Bn + Bn * Kn * 4;
    float* pcls = out + Bn + Bn * Kn * 4 + Bn * Kn;
    for (int r = tid; r < Kn; r += WT) {
        float b0 = 0.f, b1 = 0.f, b2 = 0.f, b3 = 0.f, s = 0.f, cf = -1.0f;
        if (r < num) {
            int i = idxs[r];
            b0 = x1[i]; b1 = y1[i]; b2 = x2[i]; b3 = y2[i];
            s = sc[i]; cf = (float)cl[i];
        }
        size_t base = (size_t)(b * Kn + r);
        pb[base * 4 + 0] = b0;
        pb[base * 4 + 1] = b1;
        pb[base * 4 + 2] = b2;
        pb[base * 4 + 3] = b3;
        ps[base] = s;
        pcls[base] = cf;
    }

    // ---------------- reset counters for next graph replay ----------------
    if (tid == 0) {
        g_cnt[b] = 0;
        g_cnt[Bn + b] = 0;
    }
}

// ---------------- launch ----------------
extern "C" void kernel_launch(void* const* d_in, const int* in_sizes, int n_in,
                              void* d_out, int out_size) {
    const float* tl_heat = (const float*)d_in[0];
    const float* br_heat = (const float*)d_in[1];
    const float* tl_off  = (const float*)d_in[2];
    const float* br_off  = (const float*)d_in[3];
    const float* tl_emb  = (const float*)d_in[4];
    const float* br_emb  = (const float*)d_in[5];
    const int*   inp_h   = (const int*)d_in[6];
    const int*   inp_w   = (const int*)d_in[7];
    float* out = (float*)d_out;

    k_localmax<<<TOTB, 256>>>(tl_heat, br_heat);
    k_worker<<<Bn, WT>>>(tl_heat, br_heat, tl_off, br_off, tl_emb, br_emb,
                         inp_h, inp_w, out);
}

// round 8
// speedup vs baseline: 2.1606x; 2.1606x over previous
#include <cuda_runtime.h>
#include <cstdint>

#define Bn 16
#define Cn 80
#define Hn 128
#define Wn 128
#define HWn 16384
#define Kn 100
#define NUMD 1000
#define SEGS 32
#define HI_CAP 65536
#define CAND_CAP 262144
#define PAIR_CAP 16384
#define COMP_CAP 2048
#define HALF_CAP 1024
#define SCORE_THR 0.05f
#define IOU_THR 0.5f
#define DIST_THR 0.5f
#define THR_HI 3.55f
#define TOTB (2 * Bn * Cn)
#define WT 1024   /* worker threads */

typedef unsigned long long u64;
typedef unsigned int u32;

#define NEG_INF __int_as_float(0xff800000)

// ---------------- device scratch (zero-initialized at load) ----------------
__device__ u64 g_hi[SEGS][HI_CAP];
__device__ int g_cnt[SEGS];
__device__ u64 g_low[SEGS][CAND_CAP];   // slow-path only
__device__ int g_cnt_low[SEGS];
__device__ u64 g_pairpos[Bn][PAIR_CAP]; // pair-sort overflow fallback

// ---------------- helpers ----------------
__device__ __forceinline__ u32 map_f(float f) {
    u32 u = __float_as_uint(f);
    return (u & 0x80000000u) ? ~u : (u | 0x80000000u);
}
__device__ __forceinline__ float sigmoidf_dev(float x) {
    if (x >= 0.f) return 1.f / (1.f + expf(-x));
    float e = expf(x);
    return e / (1.f + e);
}
__device__ __forceinline__ u64 make_key(float raw, u32 idx) {
    float s = sigmoidf_dev(raw);
    return ((u64)(__float_as_uint(s) | 0x80000000u) << 32) |
           (u64)(0xFFFFFFFFu - idx);
}

// ascending bitonic sort (fallback only)
__device__ __forceinline__ void bitonic_sort(u64* d, int n, int tid, int nt) {
    for (int k = 2; k <= n; k <<= 1) {
        for (int j = k >> 1; j > 0; j >>= 1) {
            for (int t = tid; t < n; t += nt) {
                int ixj = t ^ j;
                if (ixj > t) {
                    u64 a = d[t], b = d[ixj];
                    bool asc = ((t & k) == 0);
                    if ((a > b) == asc) { d[t] = b; d[ixj] = a; }
                }
            }
            __syncthreads();
        }
    }
}

// ================= K1: local-max + threshold (load-based hmax, deep MLP) =================
__global__ void __launch_bounds__(256)
k_localmax(const float* __restrict__ tl, const float* __restrict__ br) {
    const int plane = blockIdx.x;
    const int h = plane / (Bn * Cn);
    const int rem = plane % (Bn * Cn);
    const int pb = rem / Cn;
    const int pc = rem % Cn;
    const int seg = h * Bn + pb;
    const float* src = (h == 0 ? tl : br) + (size_t)rem * HWn;

    const int tid = threadIdx.x;
    const int warp = tid >> 5;
    const int lane = tid & 31;
    const int r0 = warp * 16;
    const int xb = lane * 4;
    const float4* row4 = (const float4*)src;

    // horizontal 3-max via scalar neighbor loads (L1 hits, no shuffles)
    auto loadrow = [&](int y, float4& v, float4& hm) {
        v = row4[y * 32 + lane];
        float l = (lane > 0)  ? __ldg(src + y * Wn + xb - 1) : NEG_INF;
        float r = (lane < 31) ? __ldg(src + y * Wn + xb + 4) : NEG_INF;
        hm.x = fmaxf(fmaxf(l, v.x), v.y);
        hm.y = fmaxf(fmaxf(v.x, v.y), v.z);
        hm.z = fmaxf(fmaxf(v.y, v.z), v.w);
        hm.w = fmaxf(fmaxf(v.z, v.w), r);
    };

    auto emit = [&](float v, float m, u32 idx) {
        if (v >= m) {
            int p = atomicAdd(&g_cnt[seg], 1);
            if (p < HI_CAP) g_hi[seg][p] = make_key(v, idx);
        }
    };

    float4 prev, hcarry, vcarry;
    {
        float4 dummyv;
        if (r0 > 0) loadrow(r0 - 1, dummyv, prev);
        else prev = make_float4(NEG_INF, NEG_INF, NEG_INF, NEG_INF);
        loadrow(r0, vcarry, hcarry);
    }

    #pragma unroll
    for (int c = 0; c < 4; ++c) {
        const int y = r0 + 4 * c;
        float4 va, vb, vc, vd, h1, h2, h3, h4;
        loadrow(y + 1, va, h1);
        loadrow(y + 2, vb, h2);
        loadrow(y + 3, vc, h3);
        bool has4 = (y + 4) < Hn;
        if (has4) loadrow(y + 4, vd, h4);
        else {
            vd = make_float4(0.f, 0.f, 0.f, 0.f);
            h4 = make_float4(NEG_INF, NEG_INF, NEG_INF, NEG_INF);
        }

        float4 w0, w1, w2, w3;
        w0.x = fmaxf(fmaxf(fmaxf(prev.x, hcarry.x), h1.x), THR_HI);
        w0.y = fmaxf(fmaxf(fmaxf(prev.y, hcarry.y), h1.y), THR_HI);
        w0.z = fmaxf(fmaxf(fmaxf(prev.z, hcarry.z), h1.z), THR_HI);
        w0.w = fmaxf(fmaxf(fmaxf(prev.w, hcarry.w), h1.w), THR_HI);
        w1.x = fmaxf(fmaxf(fmaxf(hcarry.x, h1.x), h2.x), THR_HI);
        w1.y = fmaxf(fmaxf(fmaxf(hcarry.y, h1.y), h2.y), THR_HI);
        w1.z = fmaxf(fmaxf(fmaxf(hcarry.z, h1.z), h2.z), THR_HI);
        w1.w = fmaxf(fmaxf(fmaxf(hcarry.w, h1.w), h2.w), THR_HI);
        w2.x = fmaxf(fmaxf(fmaxf(h1.x, h2.x), h3.x), THR_HI);
        w2.y = fmaxf(fmaxf(fmaxf(h1.y, h2.y), h3.y), THR_HI);
        w2.z = fmaxf(fmaxf(fmaxf(h1.z, h2.z), h3.z), THR_HI);
        w2.w = fmaxf(fmaxf(fmaxf(h1.w, h2.w), h3.w), THR_HI);
        w3.x = fmaxf(fmaxf(fmaxf(h2.x, h3.x), h4.x), THR_HI);
        w3.y = fmaxf(fmaxf(fmaxf(h2.y, h3.y), h4.y), THR_HI);
        w3.z = fmaxf(fmaxf(fmaxf(h2.z, h3.z), h4.z), THR_HI);
        w3.w = fmaxf(fmaxf(fmaxf(h2.w, h3.w), h4.w), THR_HI);

        bool any = (vcarry.x >= w0.x) | (vcarry.y >= w0.y) | (vcarry.z >= w0.z) | (vcarry.w >= w0.w) |
                   (va.x >= w1.x) | (va.y >= w1.y) | (va.z >= w1.z) | (va.w >= w1.w) |
                   (vb.x >= w2.x) | (vb.y >= w2.y) | (vb.z >= w2.z) | (vb.w >= w2.w) |
                   (vc.x >= w3.x) | (vc.y >= w3.y) | (vc.z >= w3.z) | (vc.w >= w3.w);

        if (__ballot_sync(0xffffffffu, any)) {
            if (any) {
                u32 ib = (u32)(pc * HWn + y * Wn + xb);
                emit(vcarry.x, w0.x, ib + 0);
                emit(vcarry.y, w0.y, ib + 1);
                emit(vcarry.z, w0.z, ib + 2);
                emit(vcarry.w, w0.w, ib + 3);
                emit(va.x, w1.x, ib + Wn + 0);
                emit(va.y, w1.y, ib + Wn + 1);
                emit(va.z, w1.z, ib + Wn + 2);
                emit(va.w, w1.w, ib + Wn + 3);
                emit(vb.x, w2.x, ib + 2 * Wn + 0);
                emit(vb.y, w2.y, ib + 2 * Wn + 1);
                emit(vb.z, w2.z, ib + 2 * Wn + 2);
                emit(vb.w, w2.w, ib + 2 * Wn + 3);
                emit(vc.x, w3.x, ib + 3 * Wn + 0);
                emit(vc.y, w3.y, ib + 3 * Wn + 1);
                emit(vc.z, w3.z, ib + 3 * Wn + 2);
                emit(vc.w, w3.w, ib + 3 * Wn + 3);
            }
        }

        prev = h3; hcarry = h4; vcarry = vd;
    }
}

// ================= K2: worker =================
__global__ void __launch_bounds__(WT)
k_worker(const float* __restrict__ tl_heat, const float* __restrict__ br_heat,
         const float* __restrict__ tl_off, const float* __restrict__ br_off,
         const float* __restrict__ tl_emb, const float* __restrict__ br_emb,
         const int* __restrict__ inp_h, const int* __restrict__ inp_w,
         float* __restrict__ out) {
    __shared__ u64 comp[COMP_CAP];          // 16KB: split [0..1024) tl / [1024..2048) br
    __shared__ u64 sel[2 * Kn];
    __shared__ float ts[Kn], tx[Kn], ty[Kn], te[Kn];
    __shared__ float bs_[Kn], bx[Kn], by[Kn], be[Kn];
    __shared__ int tc[Kn], bc[Kn];
    __shared__ float x1[NUMD], y1[NUMD], x2[NUMD], y2[NUMD], sc[NUMD];
    __shared__ unsigned char cl[NUMD], kp[NUMD];
    __shared__ short idxs[Kn];
    __shared__ int s_np, s_num;

    const int b = blockIdx.x;
    const int tid = threadIdx.x;
    const float wr = (float)(*inp_w) / (float)Wn;
    const float hr = (float)(*inp_h) / (float)Hn;

    const int m0 = g_cnt[b];
    const int m1 = g_cnt[Bn + b];
    const bool fast0 = (m0 >= Kn && m0 <= HALF_CAP);
    const bool fast1 = (m1 >= Kn && m1 <= HALF_CAP);

    // ---------------- phase 2: per-segment top-100 ----------------
    if (fast0 && fast1) {
        // both halves in parallel: warps 0-15 -> tl, warps 16-31 -> br
        const int half = tid >> 9;          // 0 or 1
        const int htid = tid & 511;
        const int seg = half * Bn + b;
        const int mhi = half ? m1 : m0;
        u64* buf = comp + half * HALF_CAP;

        for (int i = htid; i < mhi; i += 512) buf[i] = g_hi[seg][i];
        __syncthreads();

        u64 k0v = 0ull, k1v = 0ull;
        bool h0 = htid < mhi, h1 = htid + 512 < mhi;
        if (h0) k0v = buf[htid];
        if (h1) k1v = buf[htid + 512];
        int r0c = 0, r1c = 0;
        int j = 0;
        for (; j + 4 <= mhi; j += 4) {
            u64 a = buf[j], bq = buf[j + 1], cq = buf[j + 2], dq = buf[j + 3];
            r0c += (a > k0v) + (bq > k0v) + (cq > k0v) + (dq > k0v);
            r1c += (a > k1v) + (bq > k1v) + (cq > k1v) + (dq > k1v);
        }
        for (; j < mhi; ++j) {
            u64 a = buf[j];
            r0c += (a > k0v);
            r1c += (a > k1v);
        }
        if (h0 && r0c < Kn) sel[half * Kn + r0c] = k0v;
        if (h1 && r1c < Kn) sel[half * Kn + r1c] = k1v;
        __syncthreads();

        // gather: htid<Kn of each half handles its segment
        if (htid < Kn) {
            u64 key = sel[half * Kn + htid];
            u32 m = (u32)(key >> 32);
            float score = __uint_as_float(m & 0x7FFFFFFFu);
            u32 idx = 0xFFFFFFFFu - (u32)(key & 0xFFFFFFFFu);
            int cls = idx / HWn;
            int ind = idx % HWn;
            int yy = ind >> 7, xx = ind & 127;
            const float* offp = half ? br_off : tl_off;
            const float* embp = half ? br_emb : tl_emb;
            float ox = offp[((size_t)(b * 2 + 0) * HWn) + ind];
            float oy = offp[((size_t)(b * 2 + 1) * HWn) + ind];
            float em = embp[(size_t)b * HWn + ind];
            float xs = fmaxf(((float)xx + ox) * wr, 0.f);
            float ys = fmaxf(((float)yy + oy) * hr, 0.f);
            if (half == 0) {
                ts[htid] = score; tx[htid] = xs; ty[htid] = ys; te[htid] = em; tc[htid] = cls;
            } else {
                bs_[htid] = score; bx[htid] = xs; by[htid] = ys; be[htid] = em; bc[htid] = cls;
            }
        }
        __syncthreads();
    } else {
        // sequential fallback (correct for any data)
        for (int pass = 0; pass < 2; ++pass) {
            const int seg = pass * Bn + b;
            const int mhi = g_cnt[seg];

            if (mhi >= Kn && mhi <= COMP_CAP) {
                for (int i = tid; i < mhi; i += WT) comp[i] = g_hi[seg][i];
                __syncthreads();
                u64 k0v = 0ull, k1v = 0ull;
                bool h0 = tid < mhi, h1 = tid + WT < mhi;
                if (h0) k0v = comp[tid];
                if (h1) k1v = comp[tid + WT];
                int r0c = 0, r1c = 0;
                for (int j = 0; j < mhi; ++j) {
                    u64 a = comp[j];
                    r0c += (a > k0v);
                    r1c += (a > k1v);
                }
                if (h0 && r0c < Kn) sel[r0c] = k0v;
                if (h1 && r1c < Kn) sel[r1c] = k1v;
                __syncthreads();
            } else {
                // full recompute + 100x max reduction (never taken on normal data)
                const float* heat = (pass ? br_heat : tl_heat) + (size_t)(b * Cn) * HWn;
                if (tid == 0) g_cnt_low[seg] = 0;
                __syncthreads();
                for (int e = tid; e < Cn * HWn; e += WT) {
                    int cc = e >> 14;
                    int ind = e & (HWn - 1);
                    int y = ind >> 7, x = ind & 127;
                    const float* pl = heat + (size_t)cc * HWn;
                    float v = pl[ind];
                    int y0 = y > 0 ? y - 1 : 0, y1b = y < 127 ? y + 1 : 127;
                    int x0 = x > 0 ? x - 1 : 0, x1b = x < 127 ? x + 1 : 127;
                    bool mx = true;
                    for (int yy = y0; yy <= y1b; ++yy)
                        for (int xx = x0; xx <= x1b; ++xx)
                            mx &= (v >= pl[yy * Wn + xx]);
                    if (mx) {
                        int p = atomicAdd(&g_cnt_low[seg], 1);
                        if (p < CAND_CAP) g_low[seg][p] = make_key(v, (u32)(cc * HWn + ind));
                    }
                }
                __syncthreads();
                int Mc = g_cnt_low[seg];
                if (Mc > CAND_CAP) Mc = CAND_CAP;
                u64* rk = comp;
                int* ri = (int*)(comp + WT);
                for (int r = 0; r < Kn; ++r) {
                    u64 best = 0ull; int bidx = -1;
                    for (int i = tid; i < Mc; i += WT) {
                        u64 v = g_low[seg][i];
                        if (v > best) { best = v; bidx = i; }
                    }
                    rk[tid] = best; ri[tid] = bidx;
                    __syncthreads();
                    for (int s = WT / 2; s > 0; s >>= 1) {
                        if (tid < s && rk[tid + s] > rk[tid]) {
                            rk[tid] = rk[tid + s]; ri[tid] = ri[tid + s];
                        }
                        __syncthreads();
                    }
                    if (tid == 0) {
                        sel[r] = rk[0];
                        if (ri[0] >= 0) g_low[seg][ri[0]] = 0ull;
                    }
                    __syncthreads();
                }
            }

            if (tid < Kn) {
                u64 key = sel[tid];
                u32 m = (u32)(key >> 32);
                float score = __uint_as_float(m & 0x7FFFFFFFu);
                u32 idx = 0xFFFFFFFFu - (u32)(key & 0xFFFFFFFFu);
                if (key == 0ull) { idx = 0u; score = 0.f; }
                int cls = idx / HWn;
                int ind = idx % HWn;
                int yy = ind >> 7, xx = ind & 127;
                const float* offp = pass ? br_off : tl_off;
                const float* embp = pass ? br_emb : tl_emb;
                float ox = offp[((size_t)(b * 2 + 0) * HWn) + ind];
                float oy = offp[((size_t)(b * 2 + 1) * HWn) + ind];
                float em = embp[(size_t)b * HWn + ind];
                float xs = fmaxf(((float)xx + ox) * wr, 0.f);
                float ys = fmaxf(((float)yy + oy) * hr, 0.f);
                if (pass == 0) {
                    ts[tid] = score; tx[tid] = xs; ty[tid] = ys; te[tid] = em; tc[tid] = cls;
                } else {
                    bs_[tid] = score; bx[tid] = xs; by[tid] = ys; be[tid] = em; bc[tid] = cls;
                }
            }
            __syncthreads();
        }
    }

    // ---------------- phase 3: pairing + positive compaction + rank order + NMS ----------------
    if (tid == 0) s_np = 0;
    __syncthreads();

    for (int t = tid; t < Kn * Kn; t += WT) {
        int i = t / Kn, j = t % Kn;
        float scv = (ts[i] + bs_[j]) * 0.5f;
        bool neg = (tc[i] != bc[j]) || (bx[j] <= tx[i]) || (by[j] <= ty[i]) ||
                   (fabsf(te[i] - be[j]) > DIST_THR);
        if (!neg && scv > SCORE_THR) {
            int p = atomicAdd(&s_np, 1);
            u64 key = ((u64)map_f(scv) << 32) | (u64)(0xFFFFFFFFu - (u32)t);
            if (p < PAIR_CAP) g_pairpos[b][p] = key;
            if (p < COMP_CAP) comp[p] = key;
        }
    }
    __syncthreads();

    int np = s_np < PAIR_CAP ? s_np : PAIR_CAP;
    int m = np < NUMD ? np : NUMD;
    if (np > 0) {
        if (np <= COMP_CAP) {
            u64 k0v = 0ull, k1v = 0ull;
            bool h0 = tid < np, h1 = tid + WT < np;
            if (h0) k0v = comp[tid];
            if (h1) k1v = comp[tid + WT];
            int r0c = 0, r1c = 0;
            for (int j = 0; j < np; ++j) {
                u64 a = comp[j];
                r0c += (a > k0v);
                r1c += (a > k1v);
            }
            __syncthreads();
            auto place = [&](u64 key, int r) {
                if (r < NUMD) {
                    u32 mm = (u32)(key >> 32);
                    float scv = __uint_as_float(mm & 0x7FFFFFFFu);
                    u32 t = 0xFFFFFFFFu - (u32)(key & 0xFFFFFFFFu);
                    int i = t / Kn, j = t % Kn;
                    x1[r] = tx[i]; y1[r] = ty[i]; x2[r] = bx[j]; y2[r] = by[j];
                    sc[r] = scv;
                    cl[r] = (unsigned char)tc[i];
                    kp[r] = 1;
                }
            };
            if (h0) place(k0v, r0c);
            if (h1) place(k1v, r1c);
            __syncthreads();
        } else {
            u64* arr = g_pairpos[b];
            int n2 = 2;
            while (n2 < np) n2 <<= 1;
            for (int t = np + tid; t < n2; t += WT) arr[t] = 0ull;
            __syncthreads();
            bitonic_sort(arr, n2, tid, WT);
            for (int r = tid; r < m; r += WT) {
                u64 key = arr[n2 - 1 - r];
                u32 mm = (u32)(key >> 32);
                float scv = __uint_as_float(mm & 0x7FFFFFFFu);
                u32 t = 0xFFFFFFFFu - (u32)(key & 0xFFFFFFFFu);
                int i = t / Kn, j = t % Kn;
                x1[r] = tx[i]; y1[r] = ty[i]; x2[r] = bx[j]; y2[r] = by[j];
                sc[r] = scv;
                cl[r] = (unsigned char)tc[i];
                kp[r] = 1;
            }
            __syncthreads();
        }

        for (int i = 0; i < m; i++) {
            if (kp[i]) {
                float xi1 = x1[i], yi1 = y1[i], xi2 = x2[i], yi2 = y2[i];
                float ai = fmaxf(xi2 - xi1, 0.f) * fmaxf(yi2 - yi1, 0.f);
                unsigned char ci = cl[i];
                for (int j = i + 1 + tid; j < m; j += WT) {
                    if (kp[j] && cl[j] == ci) {
                        float aj = fmaxf(x2[j] - x1[j], 0.f) * fmaxf(y2[j] - y1[j], 0.f);
                        float iw = fmaxf(fminf(xi2, x2[j]) - fmaxf(xi1, x1[j]), 0.f);
                        float ih = fmaxf(fminf(yi2, y2[j]) - fmaxf(yi1, y1[j]), 0.f);
                        float inter = iw * ih;
                        float iou = inter / fmaxf(ai + aj - inter, 1e-6f);
                        if (iou > IOU_THR) kp[j] = 0;
                    }
                }
            }
            __syncthreads();
        }

        if (tid == 0) {
            int cnt = 0;
            for (int i = 0; i < m; i++) {
                if (kp[i]) {
                    if (cnt < Kn) idxs[cnt] = (short)i;
                    cnt++;
                }
            }
            s_num = cnt < Kn ? cnt : Kn;
        }
    } else {
        if (tid == 0) s_num = 0;
    }
    __syncthreads();

    // ---------------- output ----------------
    const int num = s_num;
    if (tid == 0) out[b] = (float)num;

    float* pb = out + Bn;
    float* ps = out + Bn + Bn * Kn * 4;
    float* pcls = out + Bn + Bn * Kn * 4 + Bn * Kn;
    for (int r = tid; r < Kn; r += WT) {
        float b0 = 0.f, b1 = 0.f, b2 = 0.f, b3 = 0.f, s = 0.f, cf = -1.0f;
        if (r < num) {
            int i = idxs[r];
            b0 = x1[i]; b1 = y1[i]; b2 = x2[i]; b3 = y2[i];
            s = sc[i]; cf = (float)cl[i];
        }
        size_t base = (size_t)(b * Kn + r);
        pb[base * 4 + 0] = b0;
        pb[base * 4 + 1] = b1;
        pb[base * 4 + 2] = b2;
        pb[base * 4 + 3] = b3;
        ps[base] = s;
        pcls[base] = cf;
    }

    // ---------------- reset counters for next graph replay ----------------
    if (tid == 0) {
        g_cnt[b] = 0;
        g_cnt[Bn + b] = 0;
    }
}

// ---------------- launch ----------------
extern "C" void kernel_launch(void* const* d_in, const int* in_sizes, int n_in,
                              void* d_out, int out_size) {
    const float* tl_heat = (const float*)d_in[0];
    const float* br_heat = (const float*)d_in[1];
    const float* tl_off  = (const float*)d_in[2];
    const float* br_off  = (const float*)d_in[3];
    const float* tl_emb  = (const float*)d_in[4];
    const float* br_emb  = (const float*)d_in[5];
    const int*   inp_h   = (const int*)d_in[6];
    const int*   inp_w   = (const int*)d_in[7];
    float* out = (float*)d_out;

    k_localmax<<<TOTB, 256>>>(tl_heat, br_heat);
    k_worker<<<Bn, WT>>>(tl_heat, br_heat, tl_off, br_off, tl_emb, br_emb,
                         inp_h, inp_w, out);
}

// round 9
// speedup vs baseline: 2.2939x; 1.0617x over previous
#include <cuda_runtime.h>
#include <cstdint>

#define Bn 16
#define Cn 80
#define Hn 128
#define Wn 128
#define HWn 16384
#define Kn 100
#define NUMD 1000
#define SEGS 32
#define HI_CAP 65536
#define CAND_CAP 262144
#define PAIR_CAP 16384
#define COMP_CAP 2048
#define HALF_CAP 512
#define SCORE_THR 0.05f
#define IOU_THR 0.5f
#define DIST_THR 0.5f
#define THR_HI 3.55f
#define TOTB (2 * Bn * Cn)
#define WT 512   /* worker threads */

typedef unsigned long long u64;
typedef unsigned int u32;

#define NEG_INF __int_as_float(0xff800000)

// ---------------- device scratch (zero-initialized at load) ----------------
__device__ u64 g_hi[SEGS][HI_CAP];
__device__ int g_cnt[SEGS];
__device__ u64 g_low[SEGS][CAND_CAP];   // slow-path only
__device__ int g_cnt_low[SEGS];
__device__ u64 g_pairpos[Bn][PAIR_CAP]; // pair-sort overflow fallback

// ---------------- helpers ----------------
__device__ __forceinline__ u32 map_f(float f) {
    u32 u = __float_as_uint(f);
    return (u & 0x80000000u) ? ~u : (u | 0x80000000u);
}
__device__ __forceinline__ float sigmoidf_dev(float x) {
    if (x >= 0.f) return 1.f / (1.f + expf(-x));
    float e = expf(x);
    return e / (1.f + e);
}
__device__ __forceinline__ u64 make_key(float raw, u32 idx) {
    float s = sigmoidf_dev(raw);
    return ((u64)(__float_as_uint(s) | 0x80000000u) << 32) |
           (u64)(0xFFFFFFFFu - idx);
}

// ascending bitonic sort (fallback only)
__device__ __forceinline__ void bitonic_sort(u64* d, int n, int tid, int nt) {
    for (int k = 2; k <= n; k <<= 1) {
        for (int j = k >> 1; j > 0; j >>= 1) {
            for (int t = tid; t < n; t += nt) {
                int ixj = t ^ j;
                if (ixj > t) {
                    u64 a = d[t], b = d[ixj];
                    bool asc = ((t & k) == 0);
                    if ((a > b) == asc) { d[t] = b; d[ixj] = a; }
                }
            }
            __syncthreads();
        }
    }
}

// ================= K1: local-max + threshold (load-based hmax, deep MLP) =================
__global__ void __launch_bounds__(256)
k_localmax(const float* __restrict__ tl, const float* __restrict__ br) {
    const int plane = blockIdx.x;
    const int h = plane / (Bn * Cn);
    const int rem = plane % (Bn * Cn);
    const int pb = rem / Cn;
    const int pc = rem % Cn;
    const int seg = h * Bn + pb;
    const float* src = (h == 0 ? tl : br) + (size_t)rem * HWn;

    const int tid = threadIdx.x;
    const int warp = tid >> 5;
    const int lane = tid & 31;
    const int r0 = warp * 16;
    const int xb = lane * 4;
    const float4* row4 = (const float4*)src;

    auto loadrow = [&](int y, float4& v, float4& hm) {
        v = row4[y * 32 + lane];
        float l = (lane > 0)  ? __ldg(src + y * Wn + xb - 1) : NEG_INF;
        float r = (lane < 31) ? __ldg(src + y * Wn + xb + 4) : NEG_INF;
        hm.x = fmaxf(fmaxf(l, v.x), v.y);
        hm.y = fmaxf(fmaxf(v.x, v.y), v.z);
        hm.z = fmaxf(fmaxf(v.y, v.z), v.w);
        hm.w = fmaxf(fmaxf(v.z, v.w), r);
    };

    auto emit = [&](float v, float m, u32 idx) {
        if (v >= m) {
            int p = atomicAdd(&g_cnt[seg], 1);
            if (p < HI_CAP) g_hi[seg][p] = make_key(v, idx);
        }
    };

    float4 prev, hcarry, vcarry;
    {
        float4 dummyv;
        if (r0 > 0) loadrow(r0 - 1, dummyv, prev);
        else prev = make_float4(NEG_INF, NEG_INF, NEG_INF, NEG_INF);
        loadrow(r0, vcarry, hcarry);
    }

    #pragma unroll
    for (int c = 0; c < 4; ++c) {
        const int y = r0 + 4 * c;
        float4 va, vb, vc, vd, h1, h2, h3, h4;
        loadrow(y + 1, va, h1);
        loadrow(y + 2, vb, h2);
        loadrow(y + 3, vc, h3);
        bool has4 = (y + 4) < Hn;
        if (has4) loadrow(y + 4, vd, h4);
        else {
            vd = make_float4(0.f, 0.f, 0.f, 0.f);
            h4 = make_float4(NEG_INF, NEG_INF, NEG_INF, NEG_INF);
        }

        float4 w0, w1, w2, w3;
        w0.x = fmaxf(fmaxf(fmaxf(prev.x, hcarry.x), h1.x), THR_HI);
        w0.y = fmaxf(fmaxf(fmaxf(prev.y, hcarry.y), h1.y), THR_HI);
        w0.z = fmaxf(fmaxf(fmaxf(prev.z, hcarry.z), h1.z), THR_HI);
        w0.w = fmaxf(fmaxf(fmaxf(prev.w, hcarry.w), h1.w), THR_HI);
        w1.x = fmaxf(fmaxf(fmaxf(hcarry.x, h1.x), h2.x), THR_HI);
        w1.y = fmaxf(fmaxf(fmaxf(hcarry.y, h1.y), h2.y), THR_HI);
        w1.z = fmaxf(fmaxf(fmaxf(hcarry.z, h1.z), h2.z), THR_HI);
        w1.w = fmaxf(fmaxf(fmaxf(hcarry.w, h1.w), h2.w), THR_HI);
        w2.x = fmaxf(fmaxf(fmaxf(h1.x, h2.x), h3.x), THR_HI);
        w2.y = fmaxf(fmaxf(fmaxf(h1.y, h2.y), h3.y), THR_HI);
        w2.z = fmaxf(fmaxf(fmaxf(h1.z, h2.z), h3.z), THR_HI);
        w2.w = fmaxf(fmaxf(fmaxf(h1.w, h2.w), h3.w), THR_HI);
        w3.x = fmaxf(fmaxf(fmaxf(h2.x, h3.x), h4.x), THR_HI);
        w3.y = fmaxf(fmaxf(fmaxf(h2.y, h3.y), h4.y), THR_HI);
        w3.z = fmaxf(fmaxf(fmaxf(h2.z, h3.z), h4.z), THR_HI);
        w3.w = fmaxf(fmaxf(fmaxf(h2.w, h3.w), h4.w), THR_HI);

        bool any = (vcarry.x >= w0.x) | (vcarry.y >= w0.y) | (vcarry.z >= w0.z) | (vcarry.w >= w0.w) |
                   (va.x >= w1.x) | (va.y >= w1.y) | (va.z >= w1.z) | (va.w >= w1.w) |
                   (vb.x >= w2.x) | (vb.y >= w2.y) | (vb.z >= w2.z) | (vb.w >= w2.w) |
                   (vc.x >= w3.x) | (vc.y >= w3.y) | (vc.z >= w3.z) | (vc.w >= w3.w);

        if (__ballot_sync(0xffffffffu, any)) {
            if (any) {
                u32 ib = (u32)(pc * HWn + y * Wn + xb);
                emit(vcarry.x, w0.x, ib + 0);
                emit(vcarry.y, w0.y, ib + 1);
                emit(vcarry.z, w0.z, ib + 2);
                emit(vcarry.w, w0.w, ib + 3);
                emit(va.x, w1.x, ib + Wn + 0);
                emit(va.y, w1.y, ib + Wn + 1);
                emit(va.z, w1.z, ib + Wn + 2);
                emit(va.w, w1.w, ib + Wn + 3);
                emit(vb.x, w2.x, ib + 2 * Wn + 0);
                emit(vb.y, w2.y, ib + 2 * Wn + 1);
                emit(vb.z, w2.z, ib + 2 * Wn + 2);
                emit(vb.w, w2.w, ib + 2 * Wn + 3);
                emit(vc.x, w3.x, ib + 3 * Wn + 0);
                emit(vc.y, w3.y, ib + 3 * Wn + 1);
                emit(vc.z, w3.z, ib + 3 * Wn + 2);
                emit(vc.w, w3.w, ib + 3 * Wn + 3);
            }
        }

        prev = h3; hcarry = h4; vcarry = vd;
    }

#if __CUDA_ARCH__ >= 900
    cudaTriggerProgrammaticLaunchCompletion();
#endif
}

// ================= K2: worker =================
__global__ void __launch_bounds__(WT)
k_worker(const float* __restrict__ tl_heat, const float* __restrict__ br_heat,
         const float* __restrict__ tl_off, const float* __restrict__ br_off,
         const float* __restrict__ tl_emb, const float* __restrict__ br_emb,
         const int* __restrict__ inp_h, const int* __restrict__ inp_w,
         float* __restrict__ out) {
    __shared__ u64 comp[COMP_CAP];          // 16KB: halves at [0..512) tl / [512..1024) br
    __shared__ u64 sel[2 * Kn];
    __shared__ float ts[Kn], tx[Kn], ty[Kn], te[Kn];
    __shared__ float bs_[Kn], bx[Kn], by[Kn], be[Kn];
    __shared__ int tc[Kn], bc[Kn];
    __shared__ float x1[NUMD], y1[NUMD], x2[NUMD], y2[NUMD], sc[NUMD];
    __shared__ unsigned char cl[NUMD], kp[NUMD];
    __shared__ short idxs[Kn];
    __shared__ int s_np, s_num;

    const int b = blockIdx.x;
    const int tid = threadIdx.x;
    const float wr = (float)(*inp_w) / (float)Wn;
    const float hr = (float)(*inp_h) / (float)Hn;

#if __CUDA_ARCH__ >= 900
    cudaGridDependencySynchronize();
#endif

    const int m0 = g_cnt[b];
    const int m1 = g_cnt[Bn + b];
    const bool fast0 = (m0 >= Kn && m0 <= HALF_CAP);
    const bool fast1 = (m1 >= Kn && m1 <= HALF_CAP);

    // ---------------- phase 2: per-segment top-100 ----------------
    if (fast0 && fast1) {
        // halves: threads 0-255 -> tl, 256-511 -> br
        const int half = tid >> 8;
        const int htid = tid & 255;
        const int seg = half * Bn + b;
        const int mhi = half ? m1 : m0;
        u64* buf = comp + half * HALF_CAP;

        for (int i = htid; i < mhi; i += 256) buf[i] = g_hi[seg][i];
        __syncthreads();

        // each thread owns up to 2 keys; only owners loop
        if (htid < mhi) {
            u64 k0v = buf[htid];
            bool h1 = htid + 256 < mhi;
            u64 k1v = h1 ? buf[htid + 256] : 0ull;
            int r0c = 0, r1c = 0;
            int j = 0;
            for (; j + 4 <= mhi; j += 4) {
                u64 a = buf[j], bq = buf[j + 1], cq = buf[j + 2], dq = buf[j + 3];
                r0c += (a > k0v) + (bq > k0v) + (cq > k0v) + (dq > k0v);
                r1c += (a > k1v) + (bq > k1v) + (cq > k1v) + (dq > k1v);
            }
            for (; j < mhi; ++j) {
                u64 a = buf[j];
                r0c += (a > k0v);
                r1c += (a > k1v);
            }
            if (r0c < Kn) sel[half * Kn + r0c] = k0v;
            if (h1 && r1c < Kn) sel[half * Kn + r1c] = k1v;
        }
        __syncthreads();

        if (htid < Kn) {
            u64 key = sel[half * Kn + htid];
            u32 m = (u32)(key >> 32);
            float score = __uint_as_float(m & 0x7FFFFFFFu);
            u32 idx = 0xFFFFFFFFu - (u32)(key & 0xFFFFFFFFu);
            int cls = idx / HWn;
            int ind = idx % HWn;
            int yy = ind >> 7, xx = ind & 127;
            const float* offp = half ? br_off : tl_off;
            const float* embp = half ? br_emb : tl_emb;
            float ox = offp[((size_t)(b * 2 + 0) * HWn) + ind];
            float oy = offp[((size_t)(b * 2 + 1) * HWn) + ind];
            float em = embp[(size_t)b * HWn + ind];
            float xs = fmaxf(((float)xx + ox) * wr, 0.f);
            float ys = fmaxf(((float)yy + oy) * hr, 0.f);
            if (half == 0) {
                ts[htid] = score; tx[htid] = xs; ty[htid] = ys; te[htid] = em; tc[htid] = cls;
            } else {
                bs_[htid] = score; bx[htid] = xs; by[htid] = ys; be[htid] = em; bc[htid] = cls;
            }
        }
        __syncthreads();
    } else {
        // sequential fallback (correct for any data)
        for (int pass = 0; pass < 2; ++pass) {
            const int seg = pass * Bn + b;
            const int mhi = g_cnt[seg];

            if (mhi >= Kn && mhi <= COMP_CAP) {
                for (int i = tid; i < mhi; i += WT) comp[i] = g_hi[seg][i];
                __syncthreads();
                if (tid < mhi) {
                    u64 kv[4];
                    int rc[4];
                    #pragma unroll
                    for (int q = 0; q < 4; ++q) {
                        int p = tid + q * WT;
                        kv[q] = (p < mhi) ? comp[p] : 0ull;
                        rc[q] = 0;
                    }
                    for (int j = 0; j < mhi; ++j) {
                        u64 a = comp[j];
                        #pragma unroll
                        for (int q = 0; q < 4; ++q) rc[q] += (a > kv[q]);
                    }
                    #pragma unroll
                    for (int q = 0; q < 4; ++q) {
                        int p = tid + q * WT;
                        if (p < mhi && rc[q] < Kn) sel[rc[q]] = kv[q];
                    }
                }
                __syncthreads();
            } else {
                // full recompute + 100x max reduction (never taken on normal data)
                const float* heat = (pass ? br_heat : tl_heat) + (size_t)(b * Cn) * HWn;
                if (tid == 0) g_cnt_low[seg] = 0;
                __syncthreads();
                for (int e = tid; e < Cn * HWn; e += WT) {
                    int cc = e >> 14;
                    int ind = e & (HWn - 1);
                    int y = ind >> 7, x = ind & 127;
                    const float* pl = heat + (size_t)cc * HWn;
                    float v = pl[ind];
                    int y0 = y > 0 ? y - 1 : 0, y1b = y < 127 ? y + 1 : 127;
                    int x0 = x > 0 ? x - 1 : 0, x1b = x < 127 ? x + 1 : 127;
                    bool mx = true;
                    for (int yy = y0; yy <= y1b; ++yy)
                        for (int xx = x0; xx <= x1b; ++xx)
                            mx &= (v >= pl[yy * Wn + xx]);
                    if (mx) {
                        int p = atomicAdd(&g_cnt_low[seg], 1);
                        if (p < CAND_CAP) g_low[seg][p] = make_key(v, (u32)(cc * HWn + ind));
                    }
                }
                __syncthreads();
                int Mc = g_cnt_low[seg];
                if (Mc > CAND_CAP) Mc = CAND_CAP;
                u64* rk = comp;
                int* ri = (int*)(comp + WT);
                for (int r = 0; r < Kn; ++r) {
                    u64 best = 0ull; int bidx = -1;
                    for (int i = tid; i < Mc; i += WT) {
                        u64 v = g_low[seg][i];
                        if (v > best) { best = v; bidx = i; }
                    }
                    rk[tid] = best; ri[tid] = bidx;
                    __syncthreads();
                    for (int s = WT / 2; s > 0; s >>= 1) {
                        if (tid < s && rk[tid + s] > rk[tid]) {
                            rk[tid] = rk[tid + s]; ri[tid] = ri[tid + s];
                        }
                        __syncthreads();
                    }
                    if (tid == 0) {
                        sel[r] = rk[0];
                        if (ri[0] >= 0) g_low[seg][ri[0]] = 0ull;
                    }
                    __syncthreads();
                }
            }

            if (tid < Kn) {
                u64 key = sel[tid];
                u32 m = (u32)(key >> 32);
                float score = __uint_as_float(m & 0x7FFFFFFFu);
                u32 idx = 0xFFFFFFFFu - (u32)(key & 0xFFFFFFFFu);
                if (key == 0ull) { idx = 0u; score = 0.f; }
                int cls = idx / HWn;
                int ind = idx % HWn;
                int yy = ind >> 7, xx = ind & 127;
                const float* offp = pass ? br_off : tl_off;
                const float* embp = pass ? br_emb : tl_emb;
                float ox = offp[((size_t)(b * 2 + 0) * HWn) + ind];
                float oy = offp[((size_t)(b * 2 + 1) * HWn) + ind];
                float em = embp[(size_t)b * HWn + ind];
                float xs = fmaxf(((float)xx + ox) * wr, 0.f);
                float ys = fmaxf(((float)yy + oy) * hr, 0.f);
                if (pass == 0) {
                    ts[tid] = score; tx[tid] = xs; ty[tid] = ys; te[tid] = em; tc[tid] = cls;
                } else {
                    bs_[tid] = score; bx[tid] = xs; by[tid] = ys; be[tid] = em; bc[tid] = cls;
                }
            }
            __syncthreads();
        }
    }

    // ---------------- phase 3: pairing + positive compaction + rank order + NMS ----------------
    if (tid == 0) s_np = 0;
    __syncthreads();

    for (int t = tid; t < Kn * Kn; t += WT) {
        int i = t / Kn, j = t % Kn;
        float scv = (ts[i] + bs_[j]) * 0.5f;
        bool neg = (tc[i] != bc[j]) || (bx[j] <= tx[i]) || (by[j] <= ty[i]) ||
                   (fabsf(te[i] - be[j]) > DIST_THR);
        if (!neg && scv > SCORE_THR) {
            int p = atomicAdd(&s_np, 1);
            u64 key = ((u64)map_f(scv) << 32) | (u64)(0xFFFFFFFFu - (u32)t);
            if (p < PAIR_CAP) g_pairpos[b][p] = key;
            if (p < COMP_CAP) comp[p] = key;
        }
    }
    __syncthreads();

    int np = s_np < PAIR_CAP ? s_np : PAIR_CAP;
    int m = np < NUMD ? np : NUMD;
    if (np > 0) {
        if (np <= COMP_CAP) {
            if (tid < np) {
                u64 kv[4];
                int rc[4];
                #pragma unroll
                for (int q = 0; q < 4; ++q) {
                    int p = tid + q * WT;
                    kv[q] = (p < np) ? comp[p] : 0ull;
                    rc[q] = 0;
                }
                for (int j = 0; j < np; ++j) {
                    u64 a = comp[j];
                    #pragma unroll
                    for (int q = 0; q < 4; ++q) rc[q] += (a > kv[q]);
                }
                #pragma unroll
                for (int q = 0; q < 4; ++q) {
                    int p = tid + q * WT;
                    if (p < np && rc[q] < NUMD) {
                        u64 key = kv[q];
                        int r = rc[q];
                        u32 mm = (u32)(key >> 32);
                        float scv = __uint_as_float(mm & 0x7FFFFFFFu);
                        u32 t = 0xFFFFFFFFu - (u32)(key & 0xFFFFFFFFu);
                        int i = t / Kn, j2 = t % Kn;
                        x1[r] = tx[i]; y1[r] = ty[i]; x2[r] = bx[j2]; y2[r] = by[j2];
                        sc[r] = scv;
                        cl[r] = (unsigned char)tc[i];
                        kp[r] = 1;
                    }
                }
            }
            __syncthreads();
        } else {
            u64* arr = g_pairpos[b];
            int n2 = 2;
            while (n2 < np) n2 <<= 1;
            for (int t = np + tid; t < n2; t += WT) arr[t] = 0ull;
            __syncthreads();
            bitonic_sort(arr, n2, tid, WT);
            for (int r = tid; r < m; r += WT) {
                u64 key = arr[n2 - 1 - r];
                u32 mm = (u32)(key >> 32);
                float scv = __uint_as_float(mm & 0x7FFFFFFFu);
                u32 t = 0xFFFFFFFFu - (u32)(key & 0xFFFFFFFFu);
                int i = t / Kn, j = t % Kn;
                x1[r] = tx[i]; y1[r] = ty[i]; x2[r] = bx[j]; y2[r] = by[j];
                sc[r] = scv;
                cl[r] = (unsigned char)tc[i];
                kp[r] = 1;
            }
            __syncthreads();
        }

        for (int i = 0; i < m; i++) {
            if (kp[i]) {
                float xi1 = x1[i], yi1 = y1[i], xi2 = x2[i], yi2 = y2[i];
                float ai = fmaxf(xi2 - xi1, 0.f) * fmaxf(yi2 - yi1, 0.f);
                unsigned char ci = cl[i];
                for (int j = i + 1 + tid; j < m; j += WT) {
                    if (kp[j] && cl[j] == ci) {
                        float aj = fmaxf(x2[j] - x1[j], 0.f) * fmaxf(y2[j] - y1[j], 0.f);
                        float iw = fmaxf(fminf(xi2, x2[j]) - fmaxf(xi1, x1[j]), 0.f);
                        float ih = fmaxf(fminf(yi2, y2[j]) - fmaxf(yi1, y1[j]), 0.f);
                        float inter = iw * ih;
                        float iou = inter / fmaxf(ai + aj - inter, 1e-6f);
                        if (iou > IOU_THR) kp[j] = 0;
                    }
                }
            }
            __syncthreads();
        }

        if (tid == 0) {
            int cnt = 0;
            for (int i = 0; i < m; i++) {
                if (kp[i]) {
                    if (cnt < Kn) idxs[cnt] = (short)i;
                    cnt++;
                }
            }
            s_num = cnt < Kn ? cnt : Kn;
        }
    } else {
        if (tid == 0) s_num = 0;
    }
    __syncthreads();

    // ---------------- output ----------------
    const int num = s_num;
    if (tid == 0) out[b] = (float)num;

    float* pb = out + Bn;
    float* ps = out + Bn + Bn * Kn * 4;
    float* pcls = out + Bn + Bn * Kn * 4 + Bn * Kn;
    for (int r = tid; r < Kn; r += WT) {
        float b0 = 0.f, b1 = 0.f, b2 = 0.f, b3 = 0.f, s = 0.f, cf = -1.0f;
        if (r < num) {
            int i = idxs[r];
            b0 = x1[i]; b1 = y1[i]; b2 = x2[i]; b3 = y2[i];
            s = sc[i]; cf = (float)cl[i];
        }
        size_t base = (size_t)(b * Kn + r);
        pb[base * 4 + 0] = b0;
        pb[base * 4 + 1] = b1;
        pb[base * 4 + 2] = b2;
        pb[base * 4 + 3] = b3;
        ps[base] = s;
        pcls[base] = cf;
    }

    // ---------------- reset counters for next graph replay ----------------
    if (tid == 0) {
        g_cnt[b] = 0;
        g_cnt[Bn + b] = 0;
    }
}

// ---------------- launch ----------------
extern "C" void kernel_launch(void* const* d_in, const int* in_sizes, int n_in,
                              void* d_out, int out_size) {
    const float* tl_heat = (const float*)d_in[0];
    const float* br_heat = (const float*)d_in[1];
    const float* tl_off  = (const float*)d_in[2];
    const float* br_off  = (const float*)d_in[3];
    const float* tl_emb  = (const float*)d_in[4];
    const float* br_emb  = (const float*)d_in[5];
    const int*   inp_h   = (const int*)d_in[6];
    const int*   inp_w   = (const int*)d_in[7];
    float* out = (float*)d_out;

    k_localmax<<<TOTB, 256>>>(tl_heat, br_heat);

    // PDL launch of the worker: its launch latency overlaps k_localmax's tail.
    cudaLaunchConfig_t cfg = {};
    cfg.gridDim = dim3(Bn, 1, 1);
    cfg.blockDim = dim3(WT, 1, 1);
    cfg.dynamicSmemBytes = 0;
    cudaLaunchAttribute attrs[1];
    attrs[0].id = cudaLaunchAttributeProgrammaticStreamSerialization;
    attrs[0].val.programmaticStreamSerializationAllowed = 1;
    cfg.attrs = attrs;
    cfg.numAttrs = 1;
    cudaError_t err = cudaLaunchKernelEx(&cfg, k_worker,
                                         tl_heat, br_heat, tl_off, br_off,
                                         tl_emb, br_emb, inp_h, inp_w, out);
    if (err != cudaSuccess) {
        // fallback: plain launch (still correct, just serialized)
        k_worker<<<Bn, WT>>>(tl_heat, br_heat, tl_off, br_off,
                             tl_emb, br_emb, inp_h, inp_w, out);
    }
}